// round 1
// baseline (speedup 1.0000x reference)
#include <cuda_runtime.h>
#include <math.h>

#define TPB 256

__global__ __launch_bounds__(TPB)
void ogden_kernel(const float* __restrict__ F,
                  const float* __restrict__ mu,
                  const float* __restrict__ alpha,
                  float* __restrict__ out, int n)
{
    __shared__ float sh[TPB * 9];

    const int tid = threadIdx.x;
    const size_t base  = (size_t)blockIdx.x * (TPB * 9);
    const size_t total = (size_t)n * 9;

    // Stage 9*TPB contiguous floats: 9 perfectly coalesced 128B warp loads.
    #pragma unroll
    for (int j = 0; j < 9; ++j) {
        size_t g = base + (size_t)j * TPB + tid;
        sh[j * TPB + tid] = (g < total) ? F[g] : 0.0f;
    }

    // Uniform material constants (broadcast loads, L1-resident).
    const float a2_0 = __ldg(&alpha[0]) * 0.5f;
    const float a2_1 = __ldg(&alpha[1]) * 0.5f;
    const float a2_2 = __ldg(&alpha[2]) * 0.5f;
    const float ma_0 = __ldg(&mu[0]) / __ldg(&alpha[0]);
    const float ma_1 = __ldg(&mu[1]) / __ldg(&alpha[1]);
    const float ma_2 = __ldg(&mu[2]) / __ldg(&alpha[2]);

    __syncthreads();

    const int i = blockIdx.x * TPB + tid;
    if (i >= n) return;

    // Stride-9 shared reads: gcd(9,32)=1 -> conflict-free per access.
    const float* f = sh + tid * 9;
    const float f00 = f[0], f01 = f[1], f02 = f[2];
    const float f10 = f[3], f11 = f[4], f12 = f[5];
    const float f20 = f[6], f21 = f[7], f22 = f[8];

    // C = F^T F (symmetric)
    const float c00 = f00*f00 + f10*f10 + f20*f20;
    const float c11 = f01*f01 + f11*f11 + f21*f21;
    const float c22 = f02*f02 + f12*f12 + f22*f22;
    const float c01 = f00*f01 + f10*f11 + f20*f21;
    const float c02 = f00*f02 + f10*f12 + f20*f22;
    const float c12 = f01*f02 + f11*f12 + f21*f22;

    // det(C) = det(F)^2  (cheaper & better conditioned than det of C)
    const float detF = f00*(f11*f22 - f12*f21)
                     - f01*(f10*f22 - f12*f20)
                     + f02*(f10*f21 - f11*f20);
    const float detC = detF * detF;

    // Closed-form eigenvalues of symmetric 3x3 C (Smith's trig method).
    const float q   = (c00 + c11 + c22) * (1.0f / 3.0f);
    const float b00 = c00 - q, b11 = c11 - q, b22 = c22 - q;
    const float p2  = (b00*b00 + b11*b11 + b22*b22
                      + 2.0f * (c01*c01 + c02*c02 + c12*c12)) * (1.0f / 6.0f);
    const float p   = sqrtf(p2);
    const float detB = b00*(b11*b22 - c12*c12)
                     - c01*(c01*b22 - c12*c02)
                     + c02*(c01*c12 - b11*c02);
    float r = detB / fmaxf(2.0f * p2 * p, 1e-30f);
    r = fminf(fmaxf(r, -1.0f), 1.0f);
    const float phi = acosf(r) * (1.0f / 3.0f);

    const float tp = 2.0f * p;
    const float e1 = q + tp * __cosf(phi);
    const float e3 = q + tp * __cosf(phi + 2.0943951023931953f); // +2pi/3
    const float e2 = 3.0f * q - e1 - e3;

    // Isochoric eigenvalues in log2 space: lambbar_i = e_i * detC^{-1/3}
    const float s   = __log2f(detC);          // log2 det C  (= 2 log2 J)
    const float s3  = s * (1.0f / 3.0f);
    const float l1 = __log2f(e1) - s3;
    const float l2 = __log2f(e2) - s3;
    const float l3 = __log2f(e3) - s3;

    // W_iso = sum_k (mu_k/alpha_k) * (sum_i lambbar_i^{alpha_k/2} - 3)
    const float pw0 = exp2f(a2_0*l1) + exp2f(a2_0*l2) + exp2f(a2_0*l3);
    const float pw1 = exp2f(a2_1*l1) + exp2f(a2_1*l2) + exp2f(a2_1*l3);
    const float pw2 = exp2f(a2_2*l1) + exp2f(a2_2*l2) + exp2f(a2_2*l3);
    const float Wiso = ma_0*(pw0 - 3.0f) + ma_1*(pw1 - 3.0f) + ma_2*(pw2 - 3.0f);

    // W_vol with KAPPA=100, BETA=2:  25 * (J^2 - 2 ln J - 1), J^2 = detC.
    const float lndetC = s * 0.6931471805599453f;   // ln(detC) = 2 ln J
    const float Wvol = 25.0f * (detC - lndetC - 1.0f);

    out[i] = Wiso + Wvol;
}

extern "C" void kernel_launch(void* const* d_in, const int* in_sizes, int n_in,
                              void* d_out, int out_size)
{
    const float* F     = (const float*)d_in[0];
    const float* mu    = (const float*)d_in[1];
    const float* alpha = (const float*)d_in[2];
    float* out = (float*)d_out;

    const int n = in_sizes[0] / 9;
    const int grid = (n + TPB - 1) / TPB;
    ogden_kernel<<<grid, TPB>>>(F, mu, alpha, out, n);
}

// round 2
// speedup vs baseline: 1.1579x; 1.1579x over previous
#include <cuda_runtime.h>
#include <math.h>

#define TPB 128   // threads per block
#define PPT 4     // points per thread -> 512 points per block

typedef unsigned long long ull;
struct f2 { ull v; };

// ---- packed f32x2 helpers (sm_100+) ----
__device__ __forceinline__ f2 mk2(float a, float b) {
    f2 r; unsigned ia = __float_as_uint(a), ib = __float_as_uint(b);
    asm("mov.b64 %0, {%1, %2};" : "=l"(r.v) : "r"(ia), "r"(ib));
    return r;
}
__device__ __forceinline__ void un2(f2 x, float& a, float& b) {
    unsigned ia, ib;
    asm("mov.b64 {%0, %1}, %2;" : "=r"(ia), "=r"(ib) : "l"(x.v));
    a = __uint_as_float(ia); b = __uint_as_float(ib);
}
__device__ __forceinline__ f2 bc2(float a) { return mk2(a, a); }
__device__ __forceinline__ f2 add2(f2 a, f2 b) {
    f2 r; asm("add.rn.f32x2 %0, %1, %2;" : "=l"(r.v) : "l"(a.v), "l"(b.v)); return r;
}
__device__ __forceinline__ f2 mul2(f2 a, f2 b) {
    f2 r; asm("mul.rn.f32x2 %0, %1, %2;" : "=l"(r.v) : "l"(a.v), "l"(b.v)); return r;
}
__device__ __forceinline__ f2 fma2(f2 a, f2 b, f2 c) {
    f2 r; asm("fma.rn.f32x2 %0, %1, %2, %3;" : "=l"(r.v) : "l"(a.v), "l"(b.v), "l"(c.v)); return r;
}
__device__ __forceinline__ f2 neg2(f2 a) { f2 r; r.v = a.v ^ 0x8000000080000000ull; return r; }
__device__ __forceinline__ f2 sub2(f2 a, f2 b) { return add2(a, neg2(b)); }

// ---- fast scalar MUFU helpers ----
__device__ __forceinline__ float fsqrt_(float x) { float r; asm("sqrt.approx.f32 %0, %1;" : "=f"(r) : "f"(x)); return r; }
__device__ __forceinline__ float frcp_ (float x) { float r; asm("rcp.approx.f32 %0, %1;"  : "=f"(r) : "f"(x)); return r; }
__device__ __forceinline__ float flg2_ (float x) { float r; asm("lg2.approx.f32 %0, %1;"  : "=f"(r) : "f"(x)); return r; }
__device__ __forceinline__ float fex2_ (float x) { float r; asm("ex2.approx.f32 %0, %1;"  : "=f"(r) : "f"(x)); return r; }

// acos(r)/3, branch-free, A&S 4.4.45 (abs err <= 6.7e-5 rad)
__device__ __forceinline__ float phi_third(float r) {
    float ax = fabsf(r);
    float pl = 1.5707288f + ax * (-0.2121144f + ax * (0.0742610f - ax * 0.0187293f));
    float ac = fsqrt_(fmaxf(1.0f - ax, 0.0f)) * pl;
    float a  = (r >= 0.0f) ? ac : (3.14159265358979f - ac);
    return a * (1.0f / 3.0f);
}

// Compute strain energy for TWO points packed as f32x2 lanes.
__device__ __forceinline__ f2 ogden_pair(const float* fa, const float* fb,
                                         float a20, float a21, float a22,
                                         float ma0, float ma1, float ma2)
{
    f2 F[9];
    #pragma unroll
    for (int e = 0; e < 9; ++e) F[e] = mk2(fa[e], fb[e]);
    const f2 f00 = F[0], f01 = F[1], f02 = F[2];
    const f2 f10 = F[3], f11 = F[4], f12 = F[5];
    const f2 f20 = F[6], f21 = F[7], f22 = F[8];

    // C = F^T F (symmetric)
    f2 c00 = fma2(f00, f00, fma2(f10, f10, mul2(f20, f20)));
    f2 c11 = fma2(f01, f01, fma2(f11, f11, mul2(f21, f21)));
    f2 c22 = fma2(f02, f02, fma2(f12, f12, mul2(f22, f22)));
    f2 c01 = fma2(f00, f01, fma2(f10, f11, mul2(f20, f21)));
    f2 c02 = fma2(f00, f02, fma2(f10, f12, mul2(f20, f22)));
    f2 c12 = fma2(f01, f02, fma2(f11, f12, mul2(f21, f22)));

    // det(C) = det(F)^2
    f2 m00 = fma2(f11, f22, neg2(mul2(f12, f21)));
    f2 m01 = fma2(f10, f22, neg2(mul2(f12, f20)));
    f2 m02 = fma2(f10, f21, neg2(mul2(f11, f20)));
    f2 detF = fma2(f02, m02, fma2(neg2(f01), m01, mul2(f00, m00)));
    f2 detC = mul2(detF, detF);

    // Smith's trig eigensolver for symmetric 3x3
    f2 q   = mul2(add2(add2(c00, c11), c22), bc2(1.0f / 3.0f));
    f2 b00 = sub2(c00, q), b11 = sub2(c11, q), b22 = sub2(c22, q);
    f2 off = fma2(c12, c12, fma2(c02, c02, mul2(c01, c01)));
    f2 p2  = mul2(fma2(b00, b00, fma2(b11, b11, fma2(b22, b22, mul2(off, bc2(2.0f))))),
                  bc2(1.0f / 6.0f));

    f2 t0 = fma2(b11, b22, neg2(mul2(c12, c12)));
    f2 t1 = fma2(c01, b22, neg2(mul2(c12, c02)));
    f2 t2 = fma2(c01, c12, neg2(mul2(b11, c02)));
    f2 detB = fma2(c02, t2, fma2(neg2(c01), t1, mul2(b00, t0)));

    float p2a, p2b;  un2(p2,   p2a, p2b);
    float dBa, dBb;  un2(detB, dBa, dBb);
    float pa = fsqrt_(p2a), pb = fsqrt_(p2b);
    float ra = dBa * frcp_(fmaxf(2.0f * p2a * pa, 1e-30f));
    float rb = dBb * frcp_(fmaxf(2.0f * p2b * pb, 1e-30f));
    float pha = phi_third(ra), phb = phi_third(rb);

    f2 c1 = mk2(__cosf(pha), __cosf(phb));
    f2 c3 = mk2(__cosf(pha + 2.0943951023931953f), __cosf(phb + 2.0943951023931953f));
    f2 pp = mk2(pa, pb);
    f2 tp = add2(pp, pp);                       // 2p
    f2 e1 = fma2(tp, c1, q);
    f2 e3 = fma2(tp, c3, q);
    f2 e2 = sub2(mul2(q, bc2(3.0f)), add2(e1, e3));

    // iso eigenvalues in log2 space: l_i = log2(e_i) - log2(detC)/3
    float dCa, dCb;  un2(detC, dCa, dCb);
    float sa = flg2_(dCa), sb = flg2_(dCb);
    f2 s3 = mul2(mk2(sa, sb), bc2(-1.0f / 3.0f));
    float e1a, e1b, e2a, e2b, e3a, e3b;
    un2(e1, e1a, e1b); un2(e2, e2a, e2b); un2(e3, e3a, e3b);
    f2 l1 = add2(mk2(flg2_(e1a), flg2_(e1b)), s3);
    f2 l2 = add2(mk2(flg2_(e2a), flg2_(e2b)), s3);
    f2 l3 = add2(mk2(flg2_(e3a), flg2_(e3b)), s3);

    // power sums: pw_k = sum_i 2^(a2_k * l_i)
    f2 A0 = bc2(a20), A1 = bc2(a21), A2 = bc2(a22);
    float u, v;
    f2 x;
    x = mul2(A0, l1); un2(x, u, v); float pw0a = fex2_(u), pw0b = fex2_(v);
    x = mul2(A0, l2); un2(x, u, v); pw0a += fex2_(u); pw0b += fex2_(v);
    x = mul2(A0, l3); un2(x, u, v); pw0a += fex2_(u); pw0b += fex2_(v);
    x = mul2(A1, l1); un2(x, u, v); float pw1a = fex2_(u), pw1b = fex2_(v);
    x = mul2(A1, l2); un2(x, u, v); pw1a += fex2_(u); pw1b += fex2_(v);
    x = mul2(A1, l3); un2(x, u, v); pw1a += fex2_(u); pw1b += fex2_(v);
    x = mul2(A2, l1); un2(x, u, v); float pw2a = fex2_(u), pw2b = fex2_(v);
    x = mul2(A2, l2); un2(x, u, v); pw2a += fex2_(u); pw2b += fex2_(v);
    x = mul2(A2, l3); un2(x, u, v); pw2a += fex2_(u); pw2b += fex2_(v);

    // W = W_iso + W_vol  (KAPPA=100, BETA=2 -> 25*(detC - ln(detC) - 1))
    const float LN2 = 0.6931471805599453f;
    float Wa = ma0 * (pw0a - 3.0f) + ma1 * (pw1a - 3.0f) + ma2 * (pw2a - 3.0f)
             + 25.0f * (dCa - sa * LN2 - 1.0f);
    float Wb = ma0 * (pw0b - 3.0f) + ma1 * (pw1b - 3.0f) + ma2 * (pw2b - 3.0f)
             + 25.0f * (dCb - sb * LN2 - 1.0f);
    return mk2(Wa, Wb);
}

__global__ __launch_bounds__(TPB)
void ogden_kernel(const float4* __restrict__ F4,
                  const float* __restrict__ mu,
                  const float* __restrict__ alpha,
                  float* __restrict__ out, int n)
{
    __shared__ float4 sh4[TPB * 9];

    const int t = threadIdx.x;
    const size_t base    = (size_t)blockIdx.x * (TPB * 9);
    const size_t totalF4 = ((size_t)n * 9) >> 2;   // n*9 floats / 4

    if (base + (size_t)(TPB * 9) <= totalF4) {
        #pragma unroll
        for (int j = 0; j < 9; ++j)
            sh4[j * TPB + t] = F4[base + (size_t)j * TPB + t];
    } else {
        #pragma unroll
        for (int j = 0; j < 9; ++j) {
            size_t g = base + (size_t)j * TPB + t;
            sh4[j * TPB + t] = (g < totalF4) ? F4[g] : make_float4(1.f, 0.f, 0.f, 0.f);
        }
    }

    // uniform material constants
    const float al0 = __ldg(&alpha[0]), al1 = __ldg(&alpha[1]), al2 = __ldg(&alpha[2]);
    const float a20 = al0 * 0.5f, a21 = al1 * 0.5f, a22 = al2 * 0.5f;
    const float ma0 = __ldg(&mu[0]) / al0;
    const float ma1 = __ldg(&mu[1]) / al1;
    const float ma2 = __ldg(&mu[2]) / al2;

    __syncthreads();

    // Each thread owns 4 consecutive points = 36 floats = 9 float4 (LDS.128,
    // 36-word lane stride -> conflict-free within each 8-lane phase).
    float fl[36];
    #pragma unroll
    for (int j = 0; j < 9; ++j) {
        float4 vv = sh4[t * 9 + j];
        fl[j * 4 + 0] = vv.x; fl[j * 4 + 1] = vv.y;
        fl[j * 4 + 2] = vv.z; fl[j * 4 + 3] = vv.w;
    }

    f2 w01 = ogden_pair(fl,      fl + 9,  a20, a21, a22, ma0, ma1, ma2);
    f2 w23 = ogden_pair(fl + 18, fl + 27, a20, a21, a22, ma0, ma1, ma2);

    const int pbase = (blockIdx.x * TPB + t) * PPT;
    if (pbase >= n) return;
    float w0, w1, w2, w3;
    un2(w01, w0, w1); un2(w23, w2, w3);
    if (pbase + 3 < n) {
        *reinterpret_cast<float4*>(out + pbase) = make_float4(w0, w1, w2, w3);
    } else {
        float ws[4] = {w0, w1, w2, w3};
        #pragma unroll
        for (int k = 0; k < 4; ++k)
            if (pbase + k < n) out[pbase + k] = ws[k];
    }
}

extern "C" void kernel_launch(void* const* d_in, const int* in_sizes, int n_in,
                              void* d_out, int out_size)
{
    const float4* F4   = (const float4*)d_in[0];
    const float* mu    = (const float*)d_in[1];
    const float* alpha = (const float*)d_in[2];
    float* out = (float*)d_out;

    const int n = in_sizes[0] / 9;
    const int pointsPerBlock = TPB * PPT;
    const int grid = (n + pointsPerBlock - 1) / pointsPerBlock;
    ogden_kernel<<<grid, TPB>>>(F4, mu, alpha, out, n);
}